// round 14
// baseline (speedup 1.0000x reference)
#include <cuda_runtime.h>
#include <cuda.h>
#include <cuda_fp16.h>
#include <cstdint>

// Problem constants
#define BB 4
#define SS 2048
#define DD 1024
#define NHH 16
#define ADIM 64
#define MTOT (BB*SS)          // 8192

// ---------------------------------------------------------------------------
// Scratch (allocation-free rule: __device__ globals) — all fp16
// ---------------------------------------------------------------------------
__device__ __align__(1024) __half g_qkv[(size_t)MTOT * 3 * DD];   // 48 MB
__device__ __align__(1024) __half g_o[(size_t)MTOT * DD];         // 16 MB
__device__ __align__(1024) __half g_a[(size_t)MTOT * DD];         // rounded iQ
__device__ __align__(1024) __half g_b[(size_t)3 * DD * DD];       // rounded w_qkv
__device__ __align__(1024) __half g_w[(size_t)DD * DD];           // rounded w_out

// ---------------------------------------------------------------------------
// helpers
// ---------------------------------------------------------------------------
__device__ __forceinline__ uint32_t smem_u32(const void* p) {
    uint32_t a;
    asm("{ .reg .u64 t; cvta.to.shared.u64 t, %1; cvt.u32.u64 %0, t; }" : "=r"(a) : "l"(p));
    return a;
}

__device__ __forceinline__ void mma_f16(float c[4], const uint32_t a[4],
                                        uint32_t b0, uint32_t b1) {
    asm volatile(
        "mma.sync.aligned.m16n8k16.row.col.f32.f16.f16.f32 "
        "{%0,%1,%2,%3}, {%4,%5,%6,%7}, {%8,%9}, {%0,%1,%2,%3};\n"
        : "+f"(c[0]), "+f"(c[1]), "+f"(c[2]), "+f"(c[3])
        : "r"(a[0]), "r"(a[1]), "r"(a[2]), "r"(a[3]), "r"(b0), "r"(b1));
}

#define LDM_X4(r0,r1,r2,r3, addr) \
    asm volatile("ldmatrix.sync.aligned.m8n8.x4.shared.b16 {%0,%1,%2,%3}, [%4];" \
        : "=r"(r0), "=r"(r1), "=r"(r2), "=r"(r3) : "r"(addr))

#define LDM_X4_T(r0,r1,r2,r3, addr) \
    asm volatile("ldmatrix.sync.aligned.m8n8.x4.trans.shared.b16 {%0,%1,%2,%3}, [%4];" \
        : "=r"(r0), "=r"(r1), "=r"(r2), "=r"(r3) : "r"(addr))

__device__ __forceinline__ uint32_t pack_h2(float lo, float hi) {
    __half2 h = __floats2half2_rn(lo, hi);
    return *(uint32_t*)&h;
}

#define MBARRIER_INIT(mbar, count) \
    asm volatile("mbarrier.init.shared.b64 [%0], %1;" \
        :: "r"((uint32_t)(mbar)), "r"((uint32_t)(count)) : "memory")

#define MBARRIER_EXPECT_TX(mbar, tx) \
    asm volatile("mbarrier.arrive.expect_tx.shared.b64 _, [%0], %1;" \
        :: "r"((uint32_t)(mbar)), "r"((uint32_t)(tx)) : "memory")

#define MBARRIER_ARRIVE(mbar) \
    asm volatile("mbarrier.arrive.shared.b64 _, [%0];" \
        :: "r"((uint32_t)(mbar)) : "memory")

#define MBARRIER_WAIT_PARITY(mbar, parity) do { \
    uint32_t _mbar = (uint32_t)(mbar); \
    uint32_t _parity = (uint32_t)(parity); \
    uint32_t _done; \
    asm volatile( \
        "{\n\t" \
        ".reg .pred p;\n\t" \
        "mbarrier.try_wait.parity.acquire.cta.shared::cta.b64 p, [%1], %2;\n\t" \
        "selp.b32 %0, 1, 0, p;\n\t" \
        "}" : "=r"(_done) : "r"(_mbar), "r"(_parity) : "memory"); \
    if (!_done) { \
        asm volatile( \
            "{\n\t" \
            ".reg .pred P1;\n\t" \
            "WAIT_LOOP_%=:\n\t" \
            "mbarrier.try_wait.parity.acquire.cta.shared::cta.b64 P1, [%0], %1, 0x989680;\n\t" \
            "@P1 bra.uni WAIT_DONE_%=;\n\t" \
            "bra.uni WAIT_LOOP_%=;\n\t" \
            "WAIT_DONE_%=:\n\t" \
            "}" :: "r"(_mbar), "r"(_parity) : "memory"); \
    } \
} while(0)

#define TMA_LOAD_2D(smem_addr, map_ptr, cx, cy, mbar) \
    asm volatile( \
        "cp.async.bulk.tensor.2d.shared::cta.global.tile.mbarrier::complete_tx::bytes " \
        "[%0], [%1, {%2, %3}], [%4];" \
        :: "r"((uint32_t)(smem_addr)), "l"(map_ptr), "r"((int32_t)(cx)), \
           "r"((int32_t)(cy)), "r"((uint32_t)(mbar)) : "memory")

#define FENCE_PROXY_ASYNC() \
    asm volatile("fence.proxy.async.shared::cta;" ::: "memory")

// ---------------------------------------------------------------------------
// fp32 -> fp16 pre-round, all three inputs in ONE launch.
// Each thread converts 8 elements (16B load x2, 16B store).
// ---------------------------------------------------------------------------
#define N4_A (MTOT * DD / 8)          // 1048576 uint4 outputs (iQ)
#define N4_B (3 * DD * DD / 8)        // 393216  (w_qkv)
#define N4_C (DD * DD / 8)            // 131072  (w_out)
#define N4_TOT (N4_A + N4_B + N4_C)   // 1572864

__global__ void __launch_bounds__(256) f16_round3_kernel(
    const float4* __restrict__ inA, uint4* __restrict__ outA,
    const float4* __restrict__ inB, uint4* __restrict__ outB,
    const float4* __restrict__ inC, uint4* __restrict__ outC)
{
    int i = blockIdx.x * 256 + threadIdx.x;
    const float4* src; uint4* dst; int j;
    if (i < N4_A)            { src = inA; dst = outA; j = i; }
    else if (i < N4_A + N4_B){ src = inB; dst = outB; j = i - N4_A; }
    else                     { src = inC; dst = outC; j = i - N4_A - N4_B; }
    float4 a = src[2 * j], b = src[2 * j + 1];
    uint4 o;
    o.x = pack_h2(a.x, a.y);
    o.y = pack_h2(a.z, a.w);
    o.z = pack_h2(b.x, b.y);
    o.w = pack_h2(b.z, b.w);
    dst[j] = o;
}

// ---------------------------------------------------------------------------
// fp16 GEMM: C[M,N] = A[M,K] * B[N,K]^T  (fp32 accum).
// CTA 128x128x64; 128 threads = 4 warps (2x2), warp tile 64x64.
// NEW: 2-stage pipeline + launch_bounds(128,3) -> 3 CTAs / 12 warps per SM
// (latency-bound hypothesis: 8 warps can't cover wait->LDSM->HMMA gaps).
// smem/CTA = 65.7KB; 3 x 65.7 = 197KB <= 227KB. regs capped at 170.
// ---------------------------------------------------------------------------
#define GTILE_B 16384                        // one 128x64-half tile
#define GSTAGE_B (2 * GTILE_B)               // A + B = 32768
#define GBAR_OFF (2 * GSTAGE_B)              // 65536 (1024-aligned)
#define GSM_BYTES (GBAR_OFF + 128)           // full[2] + empty[2]

template<bool HALF_OUT>
__global__ void __launch_bounds__(128, 3) gemm_f16_kernel(
    const __grid_constant__ CUtensorMap tmA,
    const __grid_constant__ CUtensorMap tmB,
    void* __restrict__ Cv, int N, int K)
{
    extern __shared__ __align__(1024) char smc[];
    const uint32_t sm_base = smem_u32(smc);
    const uint32_t barF = sm_base + GBAR_OFF;        // full[s]  @ +s*8
    const uint32_t barE = sm_base + GBAR_OFF + 16;   // empty[s] @ +s*8

    const int tid  = threadIdx.x;
    const int warp = tid >> 5, lane = tid & 31;
    const int g = lane >> 2, t = lane & 3;
    const int wm = warp & 1;        // 64-row half
    const int wn = warp >> 1;       // 64-col half
    const int m0 = blockIdx.y * 128, n0 = blockIdx.x * 128;
    const int NKT = K >> 6;

    const uint32_t laneR = lane & 15;
    const uint32_t hi    = (lane >> 4) & 1;
    const uint32_t rx    = lane & 7;

    if (tid == 0) {
        #pragma unroll
        for (int s = 0; s < 2; s++) {
            MBARRIER_INIT(barF + s * 8, 1);
            MBARRIER_INIT(barE + s * 8, 128);
        }
        FENCE_PROXY_ASYNC();
    }
    __syncthreads();

    if (tid == 0) {
        #pragma unroll
        for (int s = 0; s < 2; s++) {
            uint32_t sa = sm_base + s * GSTAGE_B;
            MBARRIER_EXPECT_TX(barF + s * 8, GSTAGE_B);
            TMA_LOAD_2D(sa,           &tmA, s * 64, m0, barF + s * 8);
            TMA_LOAD_2D(sa + GTILE_B, &tmB, s * 64, n0, barF + s * 8);
        }
    }

    float acc[4][8][4];
    #pragma unroll
    for (int i = 0; i < 4; i++)
        #pragma unroll
        for (int j = 0; j < 8; j++)
            #pragma unroll
            for (int k = 0; k < 4; k++) acc[i][j][k] = 0.f;

    for (int kt = 0; kt < NKT; kt++) {
        const int s  = kt & 1;
        const int ph = (kt >> 1) & 1;

        MBARRIER_WAIT_PARITY(barF + s * 8, ph);

        const uint32_t sA = sm_base + s * GSTAGE_B;
        const uint32_t sB = sA + GTILE_B;

        #pragma unroll
        for (int ks = 0; ks < 4; ks++) {
            const uint32_t cx = ((2u * ks + hi) ^ rx) << 4;
            uint32_t a[4][4];
            #pragma unroll
            for (int mt = 0; mt < 4; mt++)
                LDM_X4(a[mt][0], a[mt][1], a[mt][2], a[mt][3],
                       sA + (uint32_t)(wm * 64 + mt * 16 + laneR) * 128 + cx);
            #pragma unroll
            for (int p = 0; p < 4; p++) {
                uint32_t b0, b1, b2, b3;
                LDM_X4(b0, b1, b2, b3,
                       sB + (uint32_t)(wn * 64 + p * 16 + laneR) * 128 + cx);
                #pragma unroll
                for (int mt = 0; mt < 4; mt++) {
                    mma_f16(acc[mt][2 * p],     a[mt], b0, b2);
                    mma_f16(acc[mt][2 * p + 1], a[mt], b1, b3);
                }
            }
        }

        // release stage s (all LDSM results consumed by HMMAs above)
        MBARRIER_ARRIVE(barE + s * 8);

        // producer: refill stage s with k-tile kt+2 once every thread
        // (including this one, which already arrived) has released kt.
        if (tid == 0 && kt + 2 < NKT) {
            MBARRIER_WAIT_PARITY(barE + s * 8, ph);
            uint32_t sa = sm_base + s * GSTAGE_B;
            MBARRIER_EXPECT_TX(barF + s * 8, GSTAGE_B);
            TMA_LOAD_2D(sa,           &tmA, (kt + 2) * 64, m0, barF + s * 8);
            TMA_LOAD_2D(sa + GTILE_B, &tmB, (kt + 2) * 64, n0, barF + s * 8);
        }
    }

    #pragma unroll
    for (int mt = 0; mt < 4; mt++) {
        int r0 = m0 + wm * 64 + mt * 16 + g;
        #pragma unroll
        for (int nt = 0; nt < 8; nt++) {
            int c0 = n0 + wn * 64 + nt * 8 + 2 * t;
            if (HALF_OUT) {
                __half* Ch = (__half*)Cv;
                *(uint32_t*)&Ch[(size_t)r0 * N + c0]       = pack_h2(acc[mt][nt][0], acc[mt][nt][1]);
                *(uint32_t*)&Ch[(size_t)(r0 + 8) * N + c0] = pack_h2(acc[mt][nt][2], acc[mt][nt][3]);
            } else {
                float* Cf = (float*)Cv;
                *(float2*)&Cf[(size_t)r0 * N + c0]       = make_float2(acc[mt][nt][0], acc[mt][nt][1]);
                *(float2*)&Cf[(size_t)(r0 + 8) * N + c0] = make_float2(acc[mt][nt][2], acc[mt][nt][3]);
            }
        }
    }
}

// ---------------------------------------------------------------------------
// Fused squared-ReLU attention (R13 config — best measured): 128 threads =
// 4 warps, each warp owns 32 q-rows (two m16 tiles) x all 128 keys.
// TMA Q/K/V (SW128), double-buffered K/V, full/empty mbarriers. 2 CTAs/SM.
// Grid: (S/128, NH, B).
// ---------------------------------------------------------------------------
#define ATILE_B 16384
#define AQ_OFF  0
#define AK_OFF  ATILE_B                       // K0 @16K, K1 @32K
#define AV_OFF  (3 * ATILE_B)                 // V0 @48K, V1 @64K
#define ABAR_OFF (5 * ATILE_B)                // 81920 (1024-aligned)
#define ATTN_SMEM_BYTES (ABAR_OFF + 128)

__global__ void __launch_bounds__(128, 2) attn_kernel(
    const __grid_constant__ CUtensorMap tmQKV,
    const float* __restrict__ sn_bias,
    __half* __restrict__ o_out)
{
    extern __shared__ __align__(1024) char smc[];
    const uint32_t base = smem_u32(smc);
    const uint32_t barQ = base + ABAR_OFF;        // Q full
    const uint32_t barF = base + ABAR_OFF + 8;    // KV full[b]  @ +b*8
    const uint32_t barE = base + ABAR_OFF + 24;   // KV empty[b] @ +b*8

    const int tid  = threadIdx.x;
    const int warp = tid >> 5, lane = tid & 31;
    const int g = lane >> 2, t = lane & 3;
    const int qt = blockIdx.x, h = blockIdx.y, b = blockIdx.z;
    const float bias = sn_bias[0];

    const uint32_t laneR = lane & 15;
    const uint32_t hi    = (lane >> 4) & 1;
    const uint32_t rx    = lane & 7;

    const int xK = DD + h * ADIM;             // K columns in qkv
    const int xV = 2 * DD + h * ADIM;
    const int yBase = b * SS;

    if (tid == 0) {
        MBARRIER_INIT(barQ, 1);
        MBARRIER_INIT(barF + 0, 1);
        MBARRIER_INIT(barF + 8, 1);
        MBARRIER_INIT(barE + 0, 128);
        MBARRIER_INIT(barE + 8, 128);
        FENCE_PROXY_ASYNC();
    }
    __syncthreads();

    if (tid == 0) {
        MBARRIER_EXPECT_TX(barQ, ATILE_B);
        TMA_LOAD_2D(base + AQ_OFF, &tmQKV, h * ADIM, yBase + qt * 128, barQ);
        MBARRIER_EXPECT_TX(barF, 2 * ATILE_B);
        TMA_LOAD_2D(base + AK_OFF, &tmQKV, xK, yBase, barF);
        TMA_LOAD_2D(base + AV_OFF, &tmQKV, xV, yBase, barF);
    }

    // per-warp: 2 m-tiles (rows warp*32 + m*16 + {g, g+8})
    float Oacc[2][8][4];
    #pragma unroll
    for (int m = 0; m < 2; m++)
        #pragma unroll
        for (int i = 0; i < 8; i++)
            #pragma unroll
            for (int j = 0; j < 4; j++) Oacc[m][i][j] = 0.f;
    float rs[2][2] = {{0.f, 0.f}, {0.f, 0.f}};

    for (int kt = 0; kt < 16; kt++) {
        const int buf = kt & 1;

        if (tid == 0 && kt + 1 < 16) {
            const int nb = buf ^ 1;
            if (kt >= 1) MBARRIER_WAIT_PARITY(barE + nb * 8, ((kt - 1) >> 1) & 1);
            MBARRIER_EXPECT_TX(barF + nb * 8, 2 * ATILE_B);
            TMA_LOAD_2D(base + AK_OFF + nb * ATILE_B, &tmQKV, xK,
                        yBase + (kt + 1) * 128, barF + nb * 8);
            TMA_LOAD_2D(base + AV_OFF + nb * ATILE_B, &tmQKV, xV,
                        yBase + (kt + 1) * 128, barF + nb * 8);
        }

        MBARRIER_WAIT_PARITY(barF + buf * 8, (kt >> 1) & 1);
        if (kt == 0) MBARRIER_WAIT_PARITY(barQ, 0);

        const uint32_t sK = base + AK_OFF + buf * ATILE_B;
        const uint32_t sV = base + AV_OFF + buf * ATILE_B;

        // ---- S = Q K^T  (warp: 32 q-rows x 128 keys), fp32 accum
        float Sacc[2][16][4];
        #pragma unroll
        for (int m = 0; m < 2; m++)
            #pragma unroll
            for (int i = 0; i < 16; i++)
                #pragma unroll
                for (int j = 0; j < 4; j++) Sacc[m][i][j] = 0.f;

        #pragma unroll
        for (int ks = 0; ks < 4; ks++) {
            const uint32_t cx = ((2u * ks + hi) ^ rx) << 4;
            uint32_t a[2][4];
            #pragma unroll
            for (int m = 0; m < 2; m++)
                LDM_X4(a[m][0], a[m][1], a[m][2], a[m][3],
                       base + AQ_OFF + (uint32_t)(warp * 32 + m * 16 + laneR) * 128 + cx);
            #pragma unroll
            for (int p = 0; p < 8; p++) {
                uint32_t b0, b1, b2, b3;
                LDM_X4(b0, b1, b2, b3,
                       sK + (uint32_t)(p * 16 + laneR) * 128 + cx);
                #pragma unroll
                for (int m = 0; m < 2; m++) {
                    mma_f16(Sacc[m][2 * p],     a[m], b0, b2);
                    mma_f16(Sacc[m][2 * p + 1], a[m], b1, b3);
                }
            }
        }

        // ---- t = relu(S/8 + bias)^2 in place, rowsum in fp32
        #pragma unroll
        for (int m = 0; m < 2; m++)
            #pragma unroll
            for (int nt = 0; nt < 16; nt++) {
                float v0 = fmaxf(Sacc[m][nt][0] * 0.125f + bias, 0.f); v0 *= v0;
                float v1 = fmaxf(Sacc[m][nt][1] * 0.125f + bias, 0.f); v1 *= v1;
                float v2 = fmaxf(Sacc[m][nt][2] * 0.125f + bias, 0.f); v2 *= v2;
                float v3 = fmaxf(Sacc[m][nt][3] * 0.125f + bias, 0.f); v3 *= v3;
                rs[m][0] += v0 + v1;
                rs[m][1] += v2 + v3;
                Sacc[m][nt][0] = v0; Sacc[m][nt][1] = v1;
                Sacc[m][nt][2] = v2; Sacc[m][nt][3] = v3;
            }

        // ---- O += t * V : A-frag is a straight f32->f16x2 pack of Sacc
        #pragma unroll
        for (int kk = 0; kk < 8; kk++) {
            uint32_t aF[2][4];
            #pragma unroll
            for (int m = 0; m < 2; m++) {
                aF[m][0] = pack_h2(Sacc[m][2 * kk][0],     Sacc[m][2 * kk][1]);
                aF[m][1] = pack_h2(Sacc[m][2 * kk][2],     Sacc[m][2 * kk][3]);
                aF[m][2] = pack_h2(Sacc[m][2 * kk + 1][0], Sacc[m][2 * kk + 1][1]);
                aF[m][3] = pack_h2(Sacc[m][2 * kk + 1][2], Sacc[m][2 * kk + 1][3]);
            }
            const uint32_t vrow = (uint32_t)(kk * 16 + laneR) * 128;
            #pragma unroll
            for (int p = 0; p < 4; p++) {
                uint32_t b0, b1, b2, b3;
                LDM_X4_T(b0, b1, b2, b3,
                         sV + vrow + (((2u * p + hi) ^ rx) << 4));
                #pragma unroll
                for (int m = 0; m < 2; m++) {
                    mma_f16(Oacc[m][2 * p],     aF[m], b0, b1);
                    mma_f16(Oacc[m][2 * p + 1], aF[m], b2, b3);
                }
            }
        }

        MBARRIER_ARRIVE(barE + buf * 8);
    }

    // ---- normalize and write O as fp16 (feeds out-proj GEMM)
    #pragma unroll
    for (int m = 0; m < 2; m++) {
        float r0s = rs[m][0], r1s = rs[m][1];
        r0s += __shfl_xor_sync(0xffffffffu, r0s, 1);
        r0s += __shfl_xor_sync(0xffffffffu, r0s, 2);
        r1s += __shfl_xor_sync(0xffffffffu, r1s, 1);
        r1s += __shfl_xor_sync(0xffffffffu, r1s, 2);
        float inv0 = 1.f / (r0s + 1e-32f);
        float inv1 = 1.f / (r1s + 1e-32f);

        const int row0 = warp * 32 + m * 16 + g;
        size_t ob0 = ((size_t)(b * SS + qt * 128 + row0)) * DD + h * ADIM;
        size_t ob1 = ob0 + 8 * DD;
        #pragma unroll
        for (int dt = 0; dt < 8; dt++) {
            int c = dt * 8 + 2 * t;
            *(uint32_t*)&o_out[ob0 + c] = pack_h2(Oacc[m][dt][0] * inv0, Oacc[m][dt][1] * inv0);
            *(uint32_t*)&o_out[ob1 + c] = pack_h2(Oacc[m][dt][2] * inv1, Oacc[m][dt][3] * inv1);
        }
    }
}

// ---------------------------------------------------------------------------
// Host: tensor-map encoding via driver entry point
// ---------------------------------------------------------------------------
typedef CUresult (*EncodeFn)(CUtensorMap*, CUtensorMapDataType, cuuint32_t, void*,
                             const cuuint64_t*, const cuuint64_t*, const cuuint32_t*,
                             const cuuint32_t*, CUtensorMapInterleave, CUtensorMapSwizzle,
                             CUtensorMapL2promotion, CUtensorMapFloatOOBfill);

static void enc2d(EncodeFn f, CUtensorMap* m, const void* p,
                  uint64_t width, uint64_t height) {
    cuuint64_t dims[2]    = {width, height};
    cuuint64_t strides[1] = {width * sizeof(__half)};
    cuuint32_t box[2]     = {64, 128};
    cuuint32_t es[2]      = {1, 1};
    f(m, CU_TENSOR_MAP_DATA_TYPE_FLOAT16, 2, (void*)p, dims, strides, box, es,
      CU_TENSOR_MAP_INTERLEAVE_NONE, CU_TENSOR_MAP_SWIZZLE_128B,
      CU_TENSOR_MAP_L2_PROMOTION_L2_128B, CU_TENSOR_MAP_FLOAT_OOB_FILL_NONE);
}

extern "C" void kernel_launch(void* const* d_in, const int* in_sizes, int n_in,
                              void* d_out, int out_size)
{
    const float* iQ      = (const float*)d_in[0];
    const float* w_qkv   = (const float*)d_in[1];
    const float* w_out   = (const float*)d_in[2];
    const float* sn_bias = (const float*)d_in[3];
    float* out = (float*)d_out;
    (void)in_sizes; (void)n_in; (void)out_size;

    cudaFuncSetAttribute(attn_kernel,
                         cudaFuncAttributeMaxDynamicSharedMemorySize, ATTN_SMEM_BYTES);
    cudaFuncSetAttribute(gemm_f16_kernel<true>,
                         cudaFuncAttributeMaxDynamicSharedMemorySize, GSM_BYTES);
    cudaFuncSetAttribute(gemm_f16_kernel<false>,
                         cudaFuncAttributeMaxDynamicSharedMemorySize, GSM_BYTES);

    __half *qkvp = nullptr, *op = nullptr, *ap = nullptr, *bp = nullptr, *wp = nullptr;
    cudaGetSymbolAddress((void**)&qkvp, g_qkv);
    cudaGetSymbolAddress((void**)&op, g_o);
    cudaGetSymbolAddress((void**)&ap, g_a);
    cudaGetSymbolAddress((void**)&bp, g_b);
    cudaGetSymbolAddress((void**)&wp, g_w);

    void* fn = nullptr;
    cudaDriverEntryPointQueryResult qr;
    cudaGetDriverEntryPointByVersion("cuTensorMapEncodeTiled", &fn, 12000,
                                     cudaEnableDefault, &qr);
    EncodeFn enc = (EncodeFn)fn;

    CUtensorMap tmA1, tmB1, tmA2, tmB2, tmQKV;
    enc2d(enc, &tmA1, ap, DD, MTOT);          // rounded iQ    [8192,1024]
    enc2d(enc, &tmB1, bp, DD, 3 * DD);        // rounded wqkv  [3072,1024]
    enc2d(enc, &tmA2, op, DD, MTOT);          // attn out      [8192,1024]
    enc2d(enc, &tmB2, wp, DD, DD);            // rounded wout  [1024,1024]
    enc2d(enc, &tmQKV, qkvp, 3 * DD, MTOT);   // qkv           [8192,3072]

    // 0) pre-round ALL inputs to fp16 in one launch
    f16_round3_kernel<<<N4_TOT / 256, 256>>>(
        (const float4*)iQ, (uint4*)ap,
        (const float4*)w_qkv, (uint4*)bp,
        (const float4*)w_out, (uint4*)wp);

    // 1) qkv = iQ @ w_qkv^T  -> half [8192, 3072]
    gemm_f16_kernel<true><<<dim3(3 * DD / 128, MTOT / 128), 128, GSM_BYTES>>>(
        tmA1, tmB1, qkvp, 3 * DD, DD);

    // 2) fused squared-ReLU attention -> half g_o [8192, 1024]
    attn_kernel<<<dim3(SS / 128, NHH, BB), 128, ATTN_SMEM_BYTES>>>(
        tmQKV, sn_bias, op);

    // 3) out = o @ w_out^T  -> float d_out
    gemm_f16_kernel<false><<<dim3(DD / 128, MTOT / 128), 128, GSM_BYTES>>>(
        tmA2, tmB2, out, DD, DD);
}

// round 15
// speedup vs baseline: 1.0457x; 1.0457x over previous
#include <cuda_runtime.h>
#include <cuda.h>
#include <cuda_fp16.h>
#include <cstdint>

// Problem constants
#define BB 4
#define SS 2048
#define DD 1024
#define NHH 16
#define ADIM 64
#define MTOT (BB*SS)          // 8192

// ---------------------------------------------------------------------------
// Scratch (allocation-free rule: __device__ globals) — all fp16
// ---------------------------------------------------------------------------
__device__ __align__(1024) __half g_qkv[(size_t)MTOT * 3 * DD];   // 48 MB
__device__ __align__(1024) __half g_o[(size_t)MTOT * DD];         // 16 MB
__device__ __align__(1024) __half g_a[(size_t)MTOT * DD];         // rounded iQ
__device__ __align__(1024) __half g_b[(size_t)3 * DD * DD];       // rounded w_qkv
__device__ __align__(1024) __half g_w[(size_t)DD * DD];           // rounded w_out

// ---------------------------------------------------------------------------
// helpers
// ---------------------------------------------------------------------------
__device__ __forceinline__ uint32_t smem_u32(const void* p) {
    uint32_t a;
    asm("{ .reg .u64 t; cvta.to.shared.u64 t, %1; cvt.u32.u64 %0, t; }" : "=r"(a) : "l"(p));
    return a;
}

__device__ __forceinline__ void mma_f16(float c[4], const uint32_t a[4],
                                        uint32_t b0, uint32_t b1) {
    asm volatile(
        "mma.sync.aligned.m16n8k16.row.col.f32.f16.f16.f32 "
        "{%0,%1,%2,%3}, {%4,%5,%6,%7}, {%8,%9}, {%0,%1,%2,%3};\n"
        : "+f"(c[0]), "+f"(c[1]), "+f"(c[2]), "+f"(c[3])
        : "r"(a[0]), "r"(a[1]), "r"(a[2]), "r"(a[3]), "r"(b0), "r"(b1));
}

#define LDM_X4(r0,r1,r2,r3, addr) \
    asm volatile("ldmatrix.sync.aligned.m8n8.x4.shared.b16 {%0,%1,%2,%3}, [%4];" \
        : "=r"(r0), "=r"(r1), "=r"(r2), "=r"(r3) : "r"(addr))

#define LDM_X4_T(r0,r1,r2,r3, addr) \
    asm volatile("ldmatrix.sync.aligned.m8n8.x4.trans.shared.b16 {%0,%1,%2,%3}, [%4];" \
        : "=r"(r0), "=r"(r1), "=r"(r2), "=r"(r3) : "r"(addr))

__device__ __forceinline__ uint32_t pack_h2(float lo, float hi) {
    __half2 h = __floats2half2_rn(lo, hi);
    return *(uint32_t*)&h;
}

#define MBARRIER_INIT(mbar, count) \
    asm volatile("mbarrier.init.shared.b64 [%0], %1;" \
        :: "r"((uint32_t)(mbar)), "r"((uint32_t)(count)) : "memory")

#define MBARRIER_EXPECT_TX(mbar, tx) \
    asm volatile("mbarrier.arrive.expect_tx.shared.b64 _, [%0], %1;" \
        :: "r"((uint32_t)(mbar)), "r"((uint32_t)(tx)) : "memory")

#define MBARRIER_ARRIVE(mbar) \
    asm volatile("mbarrier.arrive.shared.b64 _, [%0];" \
        :: "r"((uint32_t)(mbar)) : "memory")

#define MBARRIER_WAIT_PARITY(mbar, parity) do { \
    uint32_t _mbar = (uint32_t)(mbar); \
    uint32_t _parity = (uint32_t)(parity); \
    uint32_t _done; \
    asm volatile( \
        "{\n\t" \
        ".reg .pred p;\n\t" \
        "mbarrier.try_wait.parity.acquire.cta.shared::cta.b64 p, [%1], %2;\n\t" \
        "selp.b32 %0, 1, 0, p;\n\t" \
        "}" : "=r"(_done) : "r"(_mbar), "r"(_parity) : "memory"); \
    if (!_done) { \
        asm volatile( \
            "{\n\t" \
            ".reg .pred P1;\n\t" \
            "WAIT_LOOP_%=:\n\t" \
            "mbarrier.try_wait.parity.acquire.cta.shared::cta.b64 P1, [%0], %1, 0x989680;\n\t" \
            "@P1 bra.uni WAIT_DONE_%=;\n\t" \
            "bra.uni WAIT_LOOP_%=;\n\t" \
            "WAIT_DONE_%=:\n\t" \
            "}" :: "r"(_mbar), "r"(_parity) : "memory"); \
    } \
} while(0)

#define TMA_LOAD_2D(smem_addr, map_ptr, cx, cy, mbar) \
    asm volatile( \
        "cp.async.bulk.tensor.2d.shared::cta.global.tile.mbarrier::complete_tx::bytes " \
        "[%0], [%1, {%2, %3}], [%4];" \
        :: "r"((uint32_t)(smem_addr)), "l"(map_ptr), "r"((int32_t)(cx)), \
           "r"((int32_t)(cy)), "r"((uint32_t)(mbar)) : "memory")

#define FENCE_PROXY_ASYNC() \
    asm volatile("fence.proxy.async.shared::cta;" ::: "memory")

// ---------------------------------------------------------------------------
// fp32 -> fp16 pre-round, all three inputs in ONE launch.
// ---------------------------------------------------------------------------
#define N4_A (MTOT * DD / 8)          // 1048576 uint4 outputs (iQ)
#define N4_B (3 * DD * DD / 8)        // 393216  (w_qkv)
#define N4_C (DD * DD / 8)            // 131072  (w_out)
#define N4_TOT (N4_A + N4_B + N4_C)   // 1572864

__global__ void __launch_bounds__(256) f16_round3_kernel(
    const float4* __restrict__ inA, uint4* __restrict__ outA,
    const float4* __restrict__ inB, uint4* __restrict__ outB,
    const float4* __restrict__ inC, uint4* __restrict__ outC)
{
    int i = blockIdx.x * 256 + threadIdx.x;
    const float4* src; uint4* dst; int j;
    if (i < N4_A)            { src = inA; dst = outA; j = i; }
    else if (i < N4_A + N4_B){ src = inB; dst = outB; j = i - N4_A; }
    else                     { src = inC; dst = outC; j = i - N4_A - N4_B; }
    float4 a = src[2 * j], b = src[2 * j + 1];
    uint4 o;
    o.x = pack_h2(a.x, a.y);
    o.y = pack_h2(a.z, a.w);
    o.z = pack_h2(b.x, b.y);
    o.w = pack_h2(b.z, b.w);
    dst[j] = o;
}

// ---------------------------------------------------------------------------
// fp16 GEMM (R13 champion config): C[M,N] = A[M,K] * B[N,K]^T.
// CTA 128x128x64; 128 threads = 4 warps (2x2), warp tile 64x64.
// TMA (SW128) + full/empty mbarrier producer-consumer, 3 stages, 2 CTAs/SM.
// ---------------------------------------------------------------------------
#define GTILE_B 16384                        // one 128x64-half tile
#define GSTAGE_B (2 * GTILE_B)               // A + B
#define GBAR_OFF (3 * GSTAGE_B)              // 98304 (1024-aligned)
#define GSM_BYTES (GBAR_OFF + 128)           // full[3] + empty[3]

template<bool HALF_OUT>
__global__ void __launch_bounds__(128, 2) gemm_f16_kernel(
    const __grid_constant__ CUtensorMap tmA,
    const __grid_constant__ CUtensorMap tmB,
    void* __restrict__ Cv, int N, int K)
{
    extern __shared__ __align__(1024) char smc[];
    const uint32_t sm_base = smem_u32(smc);
    const uint32_t barF = sm_base + GBAR_OFF;        // full[s]  @ +s*8
    const uint32_t barE = sm_base + GBAR_OFF + 24;   // empty[s] @ +s*8

    const int tid  = threadIdx.x;
    const int warp = tid >> 5, lane = tid & 31;
    const int g = lane >> 2, t = lane & 3;
    const int wm = warp & 1;        // 64-row half
    const int wn = warp >> 1;       // 64-col half
    const int m0 = blockIdx.y * 128, n0 = blockIdx.x * 128;
    const int NKT = K >> 6;

    const uint32_t laneR = lane & 15;
    const uint32_t hi    = (lane >> 4) & 1;
    const uint32_t rx    = lane & 7;

    if (tid == 0) {
        #pragma unroll
        for (int s = 0; s < 3; s++) {
            MBARRIER_INIT(barF + s * 8, 1);
            MBARRIER_INIT(barE + s * 8, 128);
        }
        FENCE_PROXY_ASYNC();
    }
    __syncthreads();

    if (tid == 0) {
        #pragma unroll
        for (int s = 0; s < 2; s++) {
            uint32_t sa = sm_base + s * GSTAGE_B;
            MBARRIER_EXPECT_TX(barF + s * 8, GSTAGE_B);
            TMA_LOAD_2D(sa,           &tmA, s * 64, m0, barF + s * 8);
            TMA_LOAD_2D(sa + GTILE_B, &tmB, s * 64, n0, barF + s * 8);
        }
    }

    float acc[4][8][4];
    #pragma unroll
    for (int i = 0; i < 4; i++)
        #pragma unroll
        for (int j = 0; j < 8; j++)
            #pragma unroll
            for (int k = 0; k < 4; k++) acc[i][j][k] = 0.f;

    for (int kt = 0; kt < NKT; kt++) {
        const int s = kt % 3;

        if (tid == 0 && kt + 2 < NKT) {
            const int s2 = (kt + 2) % 3;
            if (kt >= 1) MBARRIER_WAIT_PARITY(barE + s2 * 8, ((kt - 1) / 3) & 1);
            uint32_t sa = sm_base + s2 * GSTAGE_B;
            MBARRIER_EXPECT_TX(barF + s2 * 8, GSTAGE_B);
            TMA_LOAD_2D(sa,           &tmA, (kt + 2) * 64, m0, barF + s2 * 8);
            TMA_LOAD_2D(sa + GTILE_B, &tmB, (kt + 2) * 64, n0, barF + s2 * 8);
        }

        MBARRIER_WAIT_PARITY(barF + s * 8, (kt / 3) & 1);

        const uint32_t sA = sm_base + s * GSTAGE_B;
        const uint32_t sB = sA + GTILE_B;

        #pragma unroll
        for (int ks = 0; ks < 4; ks++) {
            const uint32_t cx = ((2u * ks + hi) ^ rx) << 4;
            uint32_t a[4][4];
            #pragma unroll
            for (int mt = 0; mt < 4; mt++)
                LDM_X4(a[mt][0], a[mt][1], a[mt][2], a[mt][3],
                       sA + (uint32_t)(wm * 64 + mt * 16 + laneR) * 128 + cx);
            #pragma unroll
            for (int p = 0; p < 4; p++) {
                uint32_t b0, b1, b2, b3;
                LDM_X4(b0, b1, b2, b3,
                       sB + (uint32_t)(wn * 64 + p * 16 + laneR) * 128 + cx);
                #pragma unroll
                for (int mt = 0; mt < 4; mt++) {
                    mma_f16(acc[mt][2 * p],     a[mt], b0, b2);
                    mma_f16(acc[mt][2 * p + 1], a[mt], b1, b3);
                }
            }
        }

        MBARRIER_ARRIVE(barE + s * 8);
    }

    #pragma unroll
    for (int mt = 0; mt < 4; mt++) {
        int r0 = m0 + wm * 64 + mt * 16 + g;
        #pragma unroll
        for (int nt = 0; nt < 8; nt++) {
            int c0 = n0 + wn * 64 + nt * 8 + 2 * t;
            if (HALF_OUT) {
                __half* Ch = (__half*)Cv;
                *(uint32_t*)&Ch[(size_t)r0 * N + c0]       = pack_h2(acc[mt][nt][0], acc[mt][nt][1]);
                *(uint32_t*)&Ch[(size_t)(r0 + 8) * N + c0] = pack_h2(acc[mt][nt][2], acc[mt][nt][3]);
            } else {
                float* Cf = (float*)Cv;
                *(float2*)&Cf[(size_t)r0 * N + c0]       = make_float2(acc[mt][nt][0], acc[mt][nt][1]);
                *(float2*)&Cf[(size_t)(r0 + 8) * N + c0] = make_float2(acc[mt][nt][2], acc[mt][nt][3]);
            }
        }
    }
}

// ---------------------------------------------------------------------------
// Fused squared-ReLU attention (R13 champion config): 128 threads = 4 warps,
// each warp owns 32 q-rows (two m16 tiles) x all 128 keys.
// TMA Q/K/V (SW128), double-buffered K/V, full/empty mbarriers. 2 CTAs/SM.
// Grid: (S/128, NH, B).
// ---------------------------------------------------------------------------
#define ATILE_B 16384
#define AQ_OFF  0
#define AK_OFF  ATILE_B                       // K0 @16K, K1 @32K
#define AV_OFF  (3 * ATILE_B)                 // V0 @48K, V1 @64K
#define ABAR_OFF (5 * ATILE_B)                // 81920 (1024-aligned)
#define ATTN_SMEM_BYTES (ABAR_OFF + 128)

__global__ void __launch_bounds__(128, 2) attn_kernel(
    const __grid_constant__ CUtensorMap tmQKV,
    const float* __restrict__ sn_bias,
    __half* __restrict__ o_out)
{
    extern __shared__ __align__(1024) char smc[];
    const uint32_t base = smem_u32(smc);
    const uint32_t barQ = base + ABAR_OFF;        // Q full
    const uint32_t barF = base + ABAR_OFF + 8;    // KV full[b]  @ +b*8
    const uint32_t barE = base + ABAR_OFF + 24;   // KV empty[b] @ +b*8

    const int tid  = threadIdx.x;
    const int warp = tid >> 5, lane = tid & 31;
    const int g = lane >> 2, t = lane & 3;
    const int qt = blockIdx.x, h = blockIdx.y, b = blockIdx.z;
    const float bias = sn_bias[0];

    const uint32_t laneR = lane & 15;
    const uint32_t hi    = (lane >> 4) & 1;
    const uint32_t rx    = lane & 7;

    const int xK = DD + h * ADIM;             // K columns in qkv
    const int xV = 2 * DD + h * ADIM;
    const int yBase = b * SS;

    if (tid == 0) {
        MBARRIER_INIT(barQ, 1);
        MBARRIER_INIT(barF + 0, 1);
        MBARRIER_INIT(barF + 8, 1);
        MBARRIER_INIT(barE + 0, 128);
        MBARRIER_INIT(barE + 8, 128);
        FENCE_PROXY_ASYNC();
    }
    __syncthreads();

    if (tid == 0) {
        MBARRIER_EXPECT_TX(barQ, ATILE_B);
        TMA_LOAD_2D(base + AQ_OFF, &tmQKV, h * ADIM, yBase + qt * 128, barQ);
        MBARRIER_EXPECT_TX(barF, 2 * ATILE_B);
        TMA_LOAD_2D(base + AK_OFF, &tmQKV, xK, yBase, barF);
        TMA_LOAD_2D(base + AV_OFF, &tmQKV, xV, yBase, barF);
    }

    // per-warp: 2 m-tiles (rows warp*32 + m*16 + {g, g+8})
    float Oacc[2][8][4];
    #pragma unroll
    for (int m = 0; m < 2; m++)
        #pragma unroll
        for (int i = 0; i < 8; i++)
            #pragma unroll
            for (int j = 0; j < 4; j++) Oacc[m][i][j] = 0.f;
    float rs[2][2] = {{0.f, 0.f}, {0.f, 0.f}};

    for (int kt = 0; kt < 16; kt++) {
        const int buf = kt & 1;

        if (tid == 0 && kt + 1 < 16) {
            const int nb = buf ^ 1;
            if (kt >= 1) MBARRIER_WAIT_PARITY(barE + nb * 8, ((kt - 1) >> 1) & 1);
            MBARRIER_EXPECT_TX(barF + nb * 8, 2 * ATILE_B);
            TMA_LOAD_2D(base + AK_OFF + nb * ATILE_B, &tmQKV, xK,
                        yBase + (kt + 1) * 128, barF + nb * 8);
            TMA_LOAD_2D(base + AV_OFF + nb * ATILE_B, &tmQKV, xV,
                        yBase + (kt + 1) * 128, barF + nb * 8);
        }

        MBARRIER_WAIT_PARITY(barF + buf * 8, (kt >> 1) & 1);
        if (kt == 0) MBARRIER_WAIT_PARITY(barQ, 0);

        const uint32_t sK = base + AK_OFF + buf * ATILE_B;
        const uint32_t sV = base + AV_OFF + buf * ATILE_B;

        // ---- S = Q K^T  (warp: 32 q-rows x 128 keys), fp32 accum
        float Sacc[2][16][4];
        #pragma unroll
        for (int m = 0; m < 2; m++)
            #pragma unroll
            for (int i = 0; i < 16; i++)
                #pragma unroll
                for (int j = 0; j < 4; j++) Sacc[m][i][j] = 0.f;

        #pragma unroll
        for (int ks = 0; ks < 4; ks++) {
            const uint32_t cx = ((2u * ks + hi) ^ rx) << 4;
            uint32_t a[2][4];
            #pragma unroll
            for (int m = 0; m < 2; m++)
                LDM_X4(a[m][0], a[m][1], a[m][2], a[m][3],
                       base + AQ_OFF + (uint32_t)(warp * 32 + m * 16 + laneR) * 128 + cx);
            #pragma unroll
            for (int p = 0; p < 8; p++) {
                uint32_t b0, b1, b2, b3;
                LDM_X4(b0, b1, b2, b3,
                       sK + (uint32_t)(p * 16 + laneR) * 128 + cx);
                #pragma unroll
                for (int m = 0; m < 2; m++) {
                    mma_f16(Sacc[m][2 * p],     a[m], b0, b2);
                    mma_f16(Sacc[m][2 * p + 1], a[m], b1, b3);
                }
            }
        }

        // ---- t = relu(S/8 + bias)^2 in place, rowsum in fp32
        #pragma unroll
        for (int m = 0; m < 2; m++)
            #pragma unroll
            for (int nt = 0; nt < 16; nt++) {
                float v0 = fmaxf(Sacc[m][nt][0] * 0.125f + bias, 0.f); v0 *= v0;
                float v1 = fmaxf(Sacc[m][nt][1] * 0.125f + bias, 0.f); v1 *= v1;
                float v2 = fmaxf(Sacc[m][nt][2] * 0.125f + bias, 0.f); v2 *= v2;
                float v3 = fmaxf(Sacc[m][nt][3] * 0.125f + bias, 0.f); v3 *= v3;
                rs[m][0] += v0 + v1;
                rs[m][1] += v2 + v3;
                Sacc[m][nt][0] = v0; Sacc[m][nt][1] = v1;
                Sacc[m][nt][2] = v2; Sacc[m][nt][3] = v3;
            }

        // ---- O += t * V : A-frag is a straight f32->f16x2 pack of Sacc
        #pragma unroll
        for (int kk = 0; kk < 8; kk++) {
            uint32_t aF[2][4];
            #pragma unroll
            for (int m = 0; m < 2; m++) {
                aF[m][0] = pack_h2(Sacc[m][2 * kk][0],     Sacc[m][2 * kk][1]);
                aF[m][1] = pack_h2(Sacc[m][2 * kk][2],     Sacc[m][2 * kk][3]);
                aF[m][2] = pack_h2(Sacc[m][2 * kk + 1][0], Sacc[m][2 * kk + 1][1]);
                aF[m][3] = pack_h2(Sacc[m][2 * kk + 1][2], Sacc[m][2 * kk + 1][3]);
            }
            const uint32_t vrow = (uint32_t)(kk * 16 + laneR) * 128;
            #pragma unroll
            for (int p = 0; p < 4; p++) {
                uint32_t b0, b1, b2, b3;
                LDM_X4_T(b0, b1, b2, b3,
                         sV + vrow + (((2u * p + hi) ^ rx) << 4));
                #pragma unroll
                for (int m = 0; m < 2; m++) {
                    mma_f16(Oacc[m][2 * p],     aF[m], b0, b1);
                    mma_f16(Oacc[m][2 * p + 1], aF[m], b2, b3);
                }
            }
        }

        MBARRIER_ARRIVE(barE + buf * 8);
    }

    // ---- normalize and write O as fp16 (feeds out-proj GEMM)
    #pragma unroll
    for (int m = 0; m < 2; m++) {
        float r0s = rs[m][0], r1s = rs[m][1];
        r0s += __shfl_xor_sync(0xffffffffu, r0s, 1);
        r0s += __shfl_xor_sync(0xffffffffu, r0s, 2);
        r1s += __shfl_xor_sync(0xffffffffu, r1s, 1);
        r1s += __shfl_xor_sync(0xffffffffu, r1s, 2);
        float inv0 = 1.f / (r0s + 1e-32f);
        float inv1 = 1.f / (r1s + 1e-32f);

        const int row0 = warp * 32 + m * 16 + g;
        size_t ob0 = ((size_t)(b * SS + qt * 128 + row0)) * DD + h * ADIM;
        size_t ob1 = ob0 + 8 * DD;
        #pragma unroll
        for (int dt = 0; dt < 8; dt++) {
            int c = dt * 8 + 2 * t;
            *(uint32_t*)&o_out[ob0 + c] = pack_h2(Oacc[m][dt][0] * inv0, Oacc[m][dt][1] * inv0);
            *(uint32_t*)&o_out[ob1 + c] = pack_h2(Oacc[m][dt][2] * inv1, Oacc[m][dt][3] * inv1);
        }
    }
}

// ---------------------------------------------------------------------------
// Host: tensor-map encoding via driver entry point
// ---------------------------------------------------------------------------
typedef CUresult (*EncodeFn)(CUtensorMap*, CUtensorMapDataType, cuuint32_t, void*,
                             const cuuint64_t*, const cuuint64_t*, const cuuint32_t*,
                             const cuuint32_t*, CUtensorMapInterleave, CUtensorMapSwizzle,
                             CUtensorMapL2promotion, CUtensorMapFloatOOBfill);

static void enc2d(EncodeFn f, CUtensorMap* m, const void* p,
                  uint64_t width, uint64_t height) {
    cuuint64_t dims[2]    = {width, height};
    cuuint64_t strides[1] = {width * sizeof(__half)};
    cuuint32_t box[2]     = {64, 128};
    cuuint32_t es[2]      = {1, 1};
    f(m, CU_TENSOR_MAP_DATA_TYPE_FLOAT16, 2, (void*)p, dims, strides, box, es,
      CU_TENSOR_MAP_INTERLEAVE_NONE, CU_TENSOR_MAP_SWIZZLE_128B,
      CU_TENSOR_MAP_L2_PROMOTION_L2_128B, CU_TENSOR_MAP_FLOAT_OOB_FILL_NONE);
}

extern "C" void kernel_launch(void* const* d_in, const int* in_sizes, int n_in,
                              void* d_out, int out_size)
{
    const float* iQ      = (const float*)d_in[0];
    const float* w_qkv   = (const float*)d_in[1];
    const float* w_out   = (const float*)d_in[2];
    const float* sn_bias = (const float*)d_in[3];
    float* out = (float*)d_out;
    (void)in_sizes; (void)n_in; (void)out_size;

    cudaFuncSetAttribute(attn_kernel,
                         cudaFuncAttributeMaxDynamicSharedMemorySize, ATTN_SMEM_BYTES);
    cudaFuncSetAttribute(gemm_f16_kernel<true>,
                         cudaFuncAttributeMaxDynamicSharedMemorySize, GSM_BYTES);
    cudaFuncSetAttribute(gemm_f16_kernel<false>,
                         cudaFuncAttributeMaxDynamicSharedMemorySize, GSM_BYTES);

    __half *qkvp = nullptr, *op = nullptr, *ap = nullptr, *bp = nullptr, *wp = nullptr;
    cudaGetSymbolAddress((void**)&qkvp, g_qkv);
    cudaGetSymbolAddress((void**)&op, g_o);
    cudaGetSymbolAddress((void**)&ap, g_a);
    cudaGetSymbolAddress((void**)&bp, g_b);
    cudaGetSymbolAddress((void**)&wp, g_w);

    void* fn = nullptr;
    cudaDriverEntryPointQueryResult qr;
    cudaGetDriverEntryPointByVersion("cuTensorMapEncodeTiled", &fn, 12000,
                                     cudaEnableDefault, &qr);
    EncodeFn enc = (EncodeFn)fn;

    CUtensorMap tmA1, tmB1, tmA2, tmB2, tmQKV;
    enc2d(enc, &tmA1, ap, DD, MTOT);          // rounded iQ    [8192,1024]
    enc2d(enc, &tmB1, bp, DD, 3 * DD);        // rounded wqkv  [3072,1024]
    enc2d(enc, &tmA2, op, DD, MTOT);          // attn out      [8192,1024]
    enc2d(enc, &tmB2, wp, DD, DD);            // rounded wout  [1024,1024]
    enc2d(enc, &tmQKV, qkvp, 3 * DD, MTOT);   // qkv           [8192,3072]

    // 0) pre-round ALL inputs to fp16 in one launch
    f16_round3_kernel<<<N4_TOT / 256, 256>>>(
        (const float4*)iQ, (uint4*)ap,
        (const float4*)w_qkv, (uint4*)bp,
        (const float4*)w_out, (uint4*)wp);

    // 1) qkv = iQ @ w_qkv^T  -> half [8192, 3072]
    gemm_f16_kernel<true><<<dim3(3 * DD / 128, MTOT / 128), 128, GSM_BYTES>>>(
        tmA1, tmB1, qkvp, 3 * DD, DD);

    // 2) fused squared-ReLU attention -> half g_o [8192, 1024]
    attn_kernel<<<dim3(SS / 128, NHH, BB), 128, ATTN_SMEM_BYTES>>>(
        tmQKV, sn_bias, op);

    // 3) out = o @ w_out^T  -> float d_out
    gemm_f16_kernel<false><<<dim3(DD / 128, MTOT / 128), 128, GSM_BYTES>>>(
        tmA2, tmB2, out, DD, DD);
}